// round 13
// baseline (speedup 1.0000x reference)
#include <cuda_runtime.h>
#include <cuda_fp16.h>

#define N_NODES 100000
#define N_EDGES 1000000
#define FB_GRID 592
#define FB_STRIDE (FB_GRID * 256)          // 151552
#define N4 (N_NODES * 4)                   // 400000 float4 slots
#define NP_GRID 296                        // 148 SMs x 2 CTAs
#define NP_WARPS (NP_GRID * 8)             // 2368 warps
#define NP_TSTRIDE (NP_GRID * 256u)

__device__ __half g_t[N_NODES * 64];    // [n][o][c] fp16: t[n,o,c] = sum_i v[n,i]*W[i*16+o][c]
__device__ __half g_tb[N_NODES * 16];   // [n][o]    fp16: tb[n,o] = sum_i v[n,i]*b[i*16+o]
__device__ float  g_r[N_NODES * 16];    // [n][o]    fp32: v@root + bias (node-local term)
__device__ float  g_sum[N_NODES * 16];  // scatter accumulator (zeroed by k_finalbn cleanup)
__device__ float  g_cnt[N_NODES];       // degree accumulator  (zeroed by k_finalbn cleanup)
__device__ float  g_s1[16];             // batch sum per feature   (re-zeroed by k_node_pre)
__device__ float  g_s2[16];             // batch sum-of-squares    (re-zeroed by k_node_pre)
__device__ int    g_ctr;                // grid-barrier counter    (re-zeroed by k_node_pre)

// ---------------------------------------------------------------------------
// K1 (launch 1): per-node precompute of t/tb/r + dst-degree histogram.
// g_cnt/g_sum arrive already zeroed (initial module state, then k_finalbn
// cleanup each launch). Warp-alternated phase order overlaps the histogram's
// memory work with the node loop's FMA latency.
// ---------------------------------------------------------------------------
__global__ void __launch_bounds__(256, 2) k_node_pre(
    const float* __restrict__ v,
    const float* __restrict__ enet_w,   // [256][4]
    const float* __restrict__ enet_b,   // [256]
    const float* __restrict__ root,     // [16][16] (i,o)
    const float* __restrict__ bias,     // [16]
    const int*   __restrict__ ei)       // [2][E]
{
    int t = threadIdx.x;
    int lane = t & 31;
    int warp = t >> 5;
    int cp = lane >> 4;        // which c-pair (0: c0,c1 / 1: c2,c3)
    int o = lane & 15;

    unsigned gid = blockIdx.x * 256u + t;
    if (gid < 16) { g_s1[gid] = 0.0f; g_s2[gid] = 0.0f; }
    if (gid == 16) g_ctr = 0;

    // --- register-resident weights ---
    float w0[16], w1[16], br[16];
    const float* brbase = (cp == 0) ? enet_b : root;
#pragma unroll
    for (int i = 0; i < 16; i++) {
        int j = i * 16 + o;
        float2 wp = __ldg(reinterpret_cast<const float2*>(enet_w + j * 4 + cp * 2));
        w0[i] = wp.x;
        w1[i] = wp.y;
        br[i] = __ldg(brbase + j);
    }
    float b0 = (cp == 0) ? 0.0f : bias[o];

    int wg = blockIdx.x * 8 + warp;
    const int* dstp = ei + N_EDGES;

    // two phases, order alternated by warp parity for cross-warp overlap
    for (int phase = 0; phase < 2; phase++) {
        if (((wg ^ phase) & 1) == 0) {
            // ---- degree histogram ----
            for (unsigned i = gid; i < N_EDGES; i += NP_TSTRIDE) {
                int dst = __ldg(dstp + i);
                float* cptr = g_cnt + dst;
                asm volatile("red.global.add.f32 [%0], %1;" :: "l"(cptr), "f"(1.0f) : "memory");
            }
        } else {
            // ---- node loop: 2 nodes in flight per warp ----
            for (int n0 = wg; n0 < N_NODES; n0 += 2 * NP_WARPS) {
                int n1 = n0 + NP_WARPS;
                bool has1 = (n1 < N_NODES);
                int n1c = has1 ? n1 : n0;

                const float4* vp0 = reinterpret_cast<const float4*>(v + (unsigned)n0 * 16u);
                const float4* vp1 = reinterpret_cast<const float4*>(v + (unsigned)n1c * 16u);
                float4 A0 = __ldg(vp0), A1 = __ldg(vp0 + 1), A2 = __ldg(vp0 + 2), A3 = __ldg(vp0 + 3);
                float4 B0 = __ldg(vp1), B1 = __ldg(vp1 + 1), B2 = __ldg(vp1 + 2), B3 = __ldg(vp1 + 3);

                float va[16] = {A0.x, A0.y, A0.z, A0.w, A1.x, A1.y, A1.z, A1.w,
                                A2.x, A2.y, A2.z, A2.w, A3.x, A3.y, A3.z, A3.w};
                float vb[16] = {B0.x, B0.y, B0.z, B0.w, B1.x, B1.y, B1.z, B1.w,
                                B2.x, B2.y, B2.z, B2.w, B3.x, B3.y, B3.z, B3.w};

                float x0 = 0.f, x1 = 0.f, xb = b0;
                float y0 = 0.f, y1 = 0.f, yb = b0;
#pragma unroll
                for (int i = 0; i < 16; i++) {
                    x0 = fmaf(va[i], w0[i], x0);
                    y0 = fmaf(vb[i], w0[i], y0);
                    x1 = fmaf(va[i], w1[i], x1);
                    y1 = fmaf(vb[i], w1[i], y1);
                    xb = fmaf(va[i], br[i], xb);
                    yb = fmaf(vb[i], br[i], yb);
                }

                {
                    __half2 h = __floats2half2_rn(x0, x1);
                    *reinterpret_cast<__half2*>(g_t + (unsigned)n0 * 64u + o * 4u + cp * 2u) = h;
                    if (cp == 0) g_tb[(unsigned)n0 * 16u + o] = __float2half_rn(xb);
                    else         g_r[(unsigned)n0 * 16u + o] = xb;
                }
                if (has1) {
                    __half2 h = __floats2half2_rn(y0, y1);
                    *reinterpret_cast<__half2*>(g_t + (unsigned)n1 * 64u + o * 4u + cp * 2u) = h;
                    if (cp == 0) g_tb[(unsigned)n1 * 16u + o] = __float2half_rn(yb);
                    else         g_r[(unsigned)n1 * 16u + o] = yb;
                }
            }
        }
    }
}

// ---------------------------------------------------------------------------
// K2 (launch 2): per-edge message + red.v2 scatter. 8 threads per edge;
// thread j handles outputs o = 2j, 2j+1. One LDG.128 covers the thread's
// 16B slice of the 128B t row (1 L1 line per edge).
// ---------------------------------------------------------------------------
__global__ void __launch_bounds__(256) k_edge(
    const float* __restrict__ efeat,
    const int* __restrict__ ei)   // [2][E] row0=src, row1=dst
{
    unsigned gid = blockIdx.x * 256u + threadIdx.x;
    unsigned eid = gid >> 3;       // grid sized exactly: N_EDGES*8/256
    unsigned j = gid & 7u;

    int src = __ldg(ei + eid);
    int dst = __ldg(ei + N_EDGES + eid);

    float4 ev = __ldg(reinterpret_cast<const float4*>(efeat) + eid);

    uint4 traw = __ldg(reinterpret_cast<const uint4*>(g_t + (unsigned)src * 64u + j * 8u));
    unsigned tbraw = __ldg(reinterpret_cast<const unsigned*>(g_tb + (unsigned)src * 16u + j * 2u));

#define H2F(u) __half22float2(*reinterpret_cast<__half2*>(&(u)))
    float2 p0 = H2F(traw.x);   // o=2j,   c0,c1
    float2 p1 = H2F(traw.y);   // o=2j,   c2,c3
    float2 p2 = H2F(traw.z);   // o=2j+1, c0,c1
    float2 p3 = H2F(traw.w);   // o=2j+1, c2,c3
    float2 tb2 = H2F(tbraw);
#undef H2F
    float m0 = fmaf(ev.x, p0.x, fmaf(ev.y, p0.y, fmaf(ev.z, p1.x, fmaf(ev.w, p1.y, tb2.x))));
    float m1 = fmaf(ev.x, p2.x, fmaf(ev.y, p2.y, fmaf(ev.z, p3.x, fmaf(ev.w, p3.y, tb2.y))));

    float* outp = g_sum + (unsigned)dst * 16u + j * 2u;
    asm volatile("red.global.add.v2.f32 [%0], {%1, %2};"
                 :: "l"(outp), "f"(m0), "f"(m1) : "memory");
}

// ---------------------------------------------------------------------------
// K3 (launch 3): fused finalize + BatchNorm + LeakyReLU with software grid
// barrier (592 blocks <= full residency). Self-cleans g_sum/g_cnt after
// reading so the next launch/replay starts from zeroed accumulators.
// ---------------------------------------------------------------------------
__global__ void __launch_bounds__(256) k_finalbn(
    float* __restrict__ out,
    const float* __restrict__ gamma,
    const float* __restrict__ beta)
{
    int t = threadIdx.x;
    int idx = blockIdx.x * 256 + t;
    const float4* s4 = reinterpret_cast<const float4*>(g_sum);
    const float4* r4 = reinterpret_cast<const float4*>(g_r);
    float4* s4w = reinterpret_cast<float4*>(g_sum);
    float4* o4 = reinterpret_cast<float4*>(out);
    const float4 z4 = make_float4(0.f, 0.f, 0.f, 0.f);

    float4 vals[3];
    float s1x = 0.f, s1y = 0.f, s1z = 0.f, s1w = 0.f;
    float s2x = 0.f, s2y = 0.f, s2z = 0.f, s2w = 0.f;
#pragma unroll
    for (int k = 0; k < 3; k++) {
        int i = idx + k * FB_STRIDE;
        if (i < N4) {
            int n = i >> 2;
            float cnt = g_cnt[n];            // all 4 readers of n are in this warp-instr
            float inv = 1.0f / fmaxf(cnt, 1.0f);
            float4 s = s4[i];
            float4 r = r4[i];
            // cleanup for next launch (after reads, program order within thread/warp)
            s4w[i] = z4;
            if ((i & 3) == 0) g_cnt[n] = 0.0f;
            float4 val;
            val.x = fmaf(s.x, inv, r.x);
            val.y = fmaf(s.y, inv, r.y);
            val.z = fmaf(s.z, inv, r.z);
            val.w = fmaf(s.w, inv, r.w);
            vals[k] = val;
            s1x += val.x; s1y += val.y; s1z += val.z; s1w += val.w;
            s2x = fmaf(val.x, val.x, s2x);
            s2y = fmaf(val.y, val.y, s2y);
            s2z = fmaf(val.z, val.z, s2z);
            s2w = fmaf(val.w, val.w, s2w);
        }
    }

#pragma unroll
    for (int m = 4; m <= 16; m <<= 1) {
        s1x += __shfl_xor_sync(0xffffffffu, s1x, m);
        s1y += __shfl_xor_sync(0xffffffffu, s1y, m);
        s1z += __shfl_xor_sync(0xffffffffu, s1z, m);
        s1w += __shfl_xor_sync(0xffffffffu, s1w, m);
        s2x += __shfl_xor_sync(0xffffffffu, s2x, m);
        s2y += __shfl_xor_sync(0xffffffffu, s2y, m);
        s2z += __shfl_xor_sync(0xffffffffu, s2z, m);
        s2w += __shfl_xor_sync(0xffffffffu, s2w, m);
    }
    __shared__ float sm1[8][4][4];
    __shared__ float sm2[8][4][4];
    int warp = t >> 5;
    int lane = t & 31;
    if (lane < 4) {
        sm1[warp][lane][0] = s1x; sm1[warp][lane][1] = s1y;
        sm1[warp][lane][2] = s1z; sm1[warp][lane][3] = s1w;
        sm2[warp][lane][0] = s2x; sm2[warp][lane][1] = s2y;
        sm2[warp][lane][2] = s2z; sm2[warp][lane][3] = s2w;
    }
    __syncthreads();
    if (t < 16) {
        float a1 = 0.f, a2 = 0.f;
#pragma unroll
        for (int w = 0; w < 8; w++) {
            a1 += sm1[w][t >> 2][t & 3];
            a2 += sm2[w][t >> 2][t & 3];
        }
        atomicAdd(&g_s1[t], a1);
        atomicAdd(&g_s2[t], a2);
    }

    __threadfence();
    __syncthreads();
    if (t == 0) {
        atomicAdd(&g_ctr, 1);
        while (atomicAdd(&g_ctr, 0) < FB_GRID) { }
    }
    __syncthreads();

    int ob = (idx & 3) * 4;
    const float invN = 1.0f / (float)N_NODES;
    float scale[4], shift[4];
#pragma unroll
    for (int k = 0; k < 4; k++) {
        int o = ob + k;
        float mu = __ldcg(&g_s1[o]) * invN;
        float var = __ldcg(&g_s2[o]) * invN - mu * mu;
        float sc = gamma[o] * rsqrtf(var + 1e-5f);
        scale[k] = sc;
        shift[k] = beta[o] - sc * mu;
    }
#pragma unroll
    for (int k = 0; k < 3; k++) {
        int i = idx + k * FB_STRIDE;
        if (i < N4) {
            float4 val = vals[k];
            float x0 = fmaf(val.x, scale[0], shift[0]);
            float x1 = fmaf(val.y, scale[1], shift[1]);
            float x2 = fmaf(val.z, scale[2], shift[2]);
            float x3 = fmaf(val.w, scale[3], shift[3]);
            float4 res;
            res.x = (x0 >= 0.0f) ? x0 : 0.01f * x0;
            res.y = (x1 >= 0.0f) ? x1 : 0.01f * x1;
            res.z = (x2 >= 0.0f) ? x2 : 0.01f * x2;
            res.w = (x3 >= 0.0f) ? x3 : 0.01f * x3;
            o4[i] = res;
        }
    }
}

// ---------------------------------------------------------------------------
extern "C" void kernel_launch(void* const* d_in, const int* in_sizes, int n_in,
                              void* d_out, int out_size) {
    const float* v      = (const float*)d_in[0];
    const float* e      = (const float*)d_in[1];
    const int*   ei     = (const int*)  d_in[2];
    const float* enet_w = (const float*)d_in[3];
    const float* enet_b = (const float*)d_in[4];
    const float* root   = (const float*)d_in[5];
    const float* bias   = (const float*)d_in[6];
    const float* gamma  = (const float*)d_in[7];
    const float* beta   = (const float*)d_in[8];
    float* out = (float*)d_out;

    k_node_pre<<<NP_GRID, 256>>>(v, enet_w, enet_b, root, bias, ei);  // launch 1
    k_edge    <<<(N_EDGES * 8) / 256, 256>>>(e, ei);                  // launch 2
    k_finalbn <<<FB_GRID, 256>>>(out, gamma, beta);                   // launch 3
}

// round 14
// speedup vs baseline: 1.0957x; 1.0957x over previous
#include <cuda_runtime.h>
#include <cuda_fp16.h>

#define N_NODES 100000
#define N_EDGES 1000000
#define FB_GRID 592
#define FB_STRIDE (FB_GRID * 256)          // 151552
#define N4 (N_NODES * 4)                   // 400000 float4 slots
#define NP_GRID 444                        // 148 SMs x 3 CTAs
#define NP_WARPS (NP_GRID * 8)             // 3552 warps
#define NP_TSTRIDE (NP_GRID * 256u)

__device__ __half g_t[N_NODES * 64];    // [n][o][c] fp16: t[n,o,c] = sum_i v[n,i]*W[i*16+o][c]
__device__ __half g_tb[N_NODES * 16];   // [n][o]    fp16: tb[n,o] = sum_i v[n,i]*b[i*16+o]
__device__ float  g_r[N_NODES * 16];    // [n][o]    fp32: v@root + bias (node-local term)
__device__ float  g_sum[N_NODES * 16];  // scatter accumulator (zeroed in k_node_pre)
__device__ float  g_cnt[N_NODES];       // degree accumulator (zero-init; re-zeroed by k_finalbn cleanup)
__device__ float  g_s1[16];             // batch sum per feature
__device__ float  g_s2[16];             // batch sum-of-squares per feature
__device__ int    g_ctr;                // grid-barrier counter

// ---------------------------------------------------------------------------
// K1 (launch 1): per-node precompute of t/tb/r + g_sum zeroing + dst-degree
// histogram (g_cnt arrives zeroed: initial module state / k_finalbn cleanup).
// One warp per node-pair; lane = (cp, o): cp = lane>>4, o = lane&15.
// ---------------------------------------------------------------------------
__global__ void __launch_bounds__(256) k_node_pre(
    const float* __restrict__ v,
    const float* __restrict__ enet_w,   // [256][4]
    const float* __restrict__ enet_b,   // [256]
    const float* __restrict__ root,     // [16][16] (i,o)
    const float* __restrict__ bias,     // [16]
    const int*   __restrict__ ei)       // [2][E]
{
    int t = threadIdx.x;
    int lane = t & 31;
    int warp = t >> 5;
    int cp = lane >> 4;        // which c-pair (0: c0,c1 / 1: c2,c3)
    int o = lane & 15;

    // --- zero g_sum + BN stats (g_cnt zeroed by previous finalbn cleanup) ---
    unsigned gid = blockIdx.x * 256u + t;
    const float4 z4 = make_float4(0.f, 0.f, 0.f, 0.f);
    for (unsigned i = gid; i < N4; i += NP_TSTRIDE)
        reinterpret_cast<float4*>(g_sum)[i] = z4;
    if (gid < 16) { g_s1[gid] = 0.0f; g_s2[gid] = 0.0f; }
    if (gid == 16) g_ctr = 0;

    // --- register-resident weights ---
    float w0[16], w1[16], br[16];
    const float* brbase = (cp == 0) ? enet_b : root;
#pragma unroll
    for (int i = 0; i < 16; i++) {
        int j = i * 16 + o;
        float2 wp = __ldg(reinterpret_cast<const float2*>(enet_w + j * 4 + cp * 2));
        w0[i] = wp.x;
        w1[i] = wp.y;
        br[i] = __ldg(brbase + j);
    }
    float b0 = (cp == 0) ? 0.0f : bias[o];   // r accumulates bias; tb starts at 0

    // --- node loop: 2 nodes in flight per warp (R12 form, unchanged) ---
    int wg = blockIdx.x * 8 + warp;
    for (int n0 = wg; n0 < N_NODES; n0 += 2 * NP_WARPS) {
        int n1 = n0 + NP_WARPS;
        bool has1 = (n1 < N_NODES);
        int n1c = has1 ? n1 : n0;

        const float4* vp0 = reinterpret_cast<const float4*>(v + (unsigned)n0 * 16u);
        const float4* vp1 = reinterpret_cast<const float4*>(v + (unsigned)n1c * 16u);
        float4 A0 = __ldg(vp0), A1 = __ldg(vp0 + 1), A2 = __ldg(vp0 + 2), A3 = __ldg(vp0 + 3);
        float4 B0 = __ldg(vp1), B1 = __ldg(vp1 + 1), B2 = __ldg(vp1 + 2), B3 = __ldg(vp1 + 3);

        float va[16] = {A0.x, A0.y, A0.z, A0.w, A1.x, A1.y, A1.z, A1.w,
                        A2.x, A2.y, A2.z, A2.w, A3.x, A3.y, A3.z, A3.w};
        float vb[16] = {B0.x, B0.y, B0.z, B0.w, B1.x, B1.y, B1.z, B1.w,
                        B2.x, B2.y, B2.z, B2.w, B3.x, B3.y, B3.z, B3.w};

        float x0 = 0.f, x1 = 0.f, xb = b0;
        float y0 = 0.f, y1 = 0.f, yb = b0;
#pragma unroll
        for (int i = 0; i < 16; i++) {
            x0 = fmaf(va[i], w0[i], x0);
            y0 = fmaf(vb[i], w0[i], y0);
            x1 = fmaf(va[i], w1[i], x1);
            y1 = fmaf(vb[i], w1[i], y1);
            xb = fmaf(va[i], br[i], xb);
            yb = fmaf(vb[i], br[i], yb);
        }

        {
            __half2 h = __floats2half2_rn(x0, x1);
            *reinterpret_cast<__half2*>(g_t + (unsigned)n0 * 64u + o * 4u + cp * 2u) = h;
            if (cp == 0) g_tb[(unsigned)n0 * 16u + o] = __float2half_rn(xb);
            else         g_r[(unsigned)n0 * 16u + o] = xb;
        }
        if (has1) {
            __half2 h = __floats2half2_rn(y0, y1);
            *reinterpret_cast<__half2*>(g_t + (unsigned)n1 * 64u + o * 4u + cp * 2u) = h;
            if (cp == 0) g_tb[(unsigned)n1 * 16u + o] = __float2half_rn(yb);
            else         g_r[(unsigned)n1 * 16u + o] = yb;
        }
    }

    // --- dst-degree histogram (rides in the latency stall slots) ---
    const int* dstp = ei + N_EDGES;
    for (unsigned i = gid; i < N_EDGES; i += NP_TSTRIDE) {
        int dst = __ldg(dstp + i);
        float* cptr = g_cnt + dst;
        asm volatile("red.global.add.f32 [%0], %1;" :: "l"(cptr), "f"(1.0f) : "memory");
    }
}

// ---------------------------------------------------------------------------
// K2 (launch 2): per-edge message + vector RED scatter (R12 form, minus the
// per-edge degree RED — histogram moved to k_node_pre).
// Quad of 4 threads per edge; thread j covers outputs 4j..4j+3.
// ---------------------------------------------------------------------------
__global__ void __launch_bounds__(256) k_edge(
    const float* __restrict__ efeat,
    const int* __restrict__ ei)   // [2][E] row0=src, row1=dst
{
    unsigned gid = blockIdx.x * 256u + threadIdx.x;
    unsigned eid = gid >> 2;
    unsigned j = gid & 3u;

    int src = __ldg(ei + eid);
    int dst = __ldg(ei + N_EDGES + eid);

    float4 ev = __ldg(reinterpret_cast<const float4*>(efeat) + eid);

    const uint4* tp = reinterpret_cast<const uint4*>(g_t + (unsigned)src * 64u + j * 16u);
    uint4 ta = __ldg(tp);
    uint4 tb = __ldg(tp + 1);
    uint2 tbr = __ldg(reinterpret_cast<const uint2*>(g_tb + (unsigned)src * 16u + j * 4u));

#define H2F(u) __half22float2(*reinterpret_cast<__half2*>(&(u)))
    float2 b01 = H2F(tbr.x), b23 = H2F(tbr.y);
    float2 c0 = H2F(ta.x), c1 = H2F(ta.y), c2 = H2F(ta.z), c3 = H2F(ta.w);
    float2 c4 = H2F(tb.x), c5 = H2F(tb.y), c6 = H2F(tb.z), c7 = H2F(tb.w);
#undef H2F
    float m0 = fmaf(ev.x, c0.x, fmaf(ev.y, c0.y, fmaf(ev.z, c1.x, fmaf(ev.w, c1.y, b01.x))));
    float m1 = fmaf(ev.x, c2.x, fmaf(ev.y, c2.y, fmaf(ev.z, c3.x, fmaf(ev.w, c3.y, b01.y))));
    float m2 = fmaf(ev.x, c4.x, fmaf(ev.y, c4.y, fmaf(ev.z, c5.x, fmaf(ev.w, c5.y, b23.x))));
    float m3 = fmaf(ev.x, c6.x, fmaf(ev.y, c6.y, fmaf(ev.z, c7.x, fmaf(ev.w, c7.y, b23.y))));

    float* outp = g_sum + (unsigned)dst * 16u + j * 4u;
    asm volatile("red.global.add.v4.f32 [%0], {%1, %2, %3, %4};"
                 :: "l"(outp), "f"(m0), "f"(m1), "f"(m2), "f"(m3) : "memory");
}

// ---------------------------------------------------------------------------
// K3 (launch 3): fused finalize + BatchNorm + LeakyReLU with software grid
// barrier (592 blocks <= full residency). Cleans g_cnt after reading so the
// next launch/replay starts from a zeroed histogram.
// ---------------------------------------------------------------------------
__global__ void __launch_bounds__(256) k_finalbn(
    float* __restrict__ out,
    const float* __restrict__ gamma,
    const float* __restrict__ beta)
{
    int t = threadIdx.x;
    int idx = blockIdx.x * 256 + t;
    const float4* s4 = reinterpret_cast<const float4*>(g_sum);
    const float4* r4 = reinterpret_cast<const float4*>(g_r);
    float4* o4 = reinterpret_cast<float4*>(out);

    float4 vals[3];
    float s1x = 0.f, s1y = 0.f, s1z = 0.f, s1w = 0.f;
    float s2x = 0.f, s2y = 0.f, s2z = 0.f, s2w = 0.f;
#pragma unroll
    for (int k = 0; k < 3; k++) {
        int i = idx + k * FB_STRIDE;
        if (i < N4) {
            int n = i >> 2;
            float cnt = g_cnt[n];      // 4 readers of n are lanes of this warp-instr
            float inv = 1.0f / fmaxf(cnt, 1.0f);
            float4 s = s4[i];
            float4 r = r4[i];
            if ((i & 3) == 0) g_cnt[n] = 0.0f;   // cleanup for next launch
            float4 val;
            val.x = fmaf(s.x, inv, r.x);
            val.y = fmaf(s.y, inv, r.y);
            val.z = fmaf(s.z, inv, r.z);
            val.w = fmaf(s.w, inv, r.w);
            vals[k] = val;
            s1x += val.x; s1y += val.y; s1z += val.z; s1w += val.w;
            s2x = fmaf(val.x, val.x, s2x);
            s2y = fmaf(val.y, val.y, s2y);
            s2z = fmaf(val.z, val.z, s2z);
            s2w = fmaf(val.w, val.w, s2w);
        }
    }

#pragma unroll
    for (int m = 4; m <= 16; m <<= 1) {
        s1x += __shfl_xor_sync(0xffffffffu, s1x, m);
        s1y += __shfl_xor_sync(0xffffffffu, s1y, m);
        s1z += __shfl_xor_sync(0xffffffffu, s1z, m);
        s1w += __shfl_xor_sync(0xffffffffu, s1w, m);
        s2x += __shfl_xor_sync(0xffffffffu, s2x, m);
        s2y += __shfl_xor_sync(0xffffffffu, s2y, m);
        s2z += __shfl_xor_sync(0xffffffffu, s2z, m);
        s2w += __shfl_xor_sync(0xffffffffu, s2w, m);
    }
    __shared__ float sm1[8][4][4];
    __shared__ float sm2[8][4][4];
    int warp = t >> 5;
    int lane = t & 31;
    if (lane < 4) {
        sm1[warp][lane][0] = s1x; sm1[warp][lane][1] = s1y;
        sm1[warp][lane][2] = s1z; sm1[warp][lane][3] = s1w;
        sm2[warp][lane][0] = s2x; sm2[warp][lane][1] = s2y;
        sm2[warp][lane][2] = s2z; sm2[warp][lane][3] = s2w;
    }
    __syncthreads();
    if (t < 16) {
        float a1 = 0.f, a2 = 0.f;
#pragma unroll
        for (int w = 0; w < 8; w++) {
            a1 += sm1[w][t >> 2][t & 3];
            a2 += sm2[w][t >> 2][t & 3];
        }
        atomicAdd(&g_s1[t], a1);
        atomicAdd(&g_s2[t], a2);
    }

    __threadfence();
    __syncthreads();
    if (t == 0) {
        atomicAdd(&g_ctr, 1);
        while (atomicAdd(&g_ctr, 0) < FB_GRID) { }
    }
    __syncthreads();

    int ob = (idx & 3) * 4;
    const float invN = 1.0f / (float)N_NODES;
    float scale[4], shift[4];
#pragma unroll
    for (int k = 0; k < 4; k++) {
        int o = ob + k;
        float mu = __ldcg(&g_s1[o]) * invN;
        float var = __ldcg(&g_s2[o]) * invN - mu * mu;
        float sc = gamma[o] * rsqrtf(var + 1e-5f);
        scale[k] = sc;
        shift[k] = beta[o] - sc * mu;
    }
#pragma unroll
    for (int k = 0; k < 3; k++) {
        int i = idx + k * FB_STRIDE;
        if (i < N4) {
            float4 val = vals[k];
            float x0 = fmaf(val.x, scale[0], shift[0]);
            float x1 = fmaf(val.y, scale[1], shift[1]);
            float x2 = fmaf(val.z, scale[2], shift[2]);
            float x3 = fmaf(val.w, scale[3], shift[3]);
            float4 res;
            res.x = (x0 >= 0.0f) ? x0 : 0.01f * x0;
            res.y = (x1 >= 0.0f) ? x1 : 0.01f * x1;
            res.z = (x2 >= 0.0f) ? x2 : 0.01f * x2;
            res.w = (x3 >= 0.0f) ? x3 : 0.01f * x3;
            o4[i] = res;
        }
    }
}

// ---------------------------------------------------------------------------
extern "C" void kernel_launch(void* const* d_in, const int* in_sizes, int n_in,
                              void* d_out, int out_size) {
    const float* v      = (const float*)d_in[0];
    const float* e      = (const float*)d_in[1];
    const int*   ei     = (const int*)  d_in[2];
    const float* enet_w = (const float*)d_in[3];
    const float* enet_b = (const float*)d_in[4];
    const float* root   = (const float*)d_in[5];
    const float* bias   = (const float*)d_in[6];
    const float* gamma  = (const float*)d_in[7];
    const float* beta   = (const float*)d_in[8];
    float* out = (float*)d_out;

    k_node_pre<<<NP_GRID, 256>>>(v, enet_w, enet_b, root, bias, ei);  // launch 1
    k_edge    <<<(N_EDGES * 4) / 256, 256>>>(e, ei);                  // launch 2
    k_finalbn <<<FB_GRID, 256>>>(out, gamma, beta);                   // launch 3
}

// round 15
// speedup vs baseline: 1.1470x; 1.0468x over previous
#include <cuda_runtime.h>
#include <cuda_fp16.h>

#define N_NODES 100000
#define N_EDGES 1000000
#define FB_GRID 592
#define FB_STRIDE (FB_GRID * 256)          // 151552
#define N4 (N_NODES * 4)                   // 400000 float4 slots
#define NP_GRID 444                        // 148 SMs x 3 CTAs
#define NP_WARPS (NP_GRID * 8)             // 3552 warps
#define NP_TSTRIDE (NP_GRID * 256u)        // 113664 threads

__device__ __half g_t[N_NODES * 64];    // [n][o][c] fp16: t[n,o,c] = sum_i v[n,i]*W[i*16+o][c]
__device__ __half g_tb[N_NODES * 16];   // [n][o]    fp16: tb[n,o] = sum_i v[n,i]*b[i*16+o]
__device__ float  g_r[N_NODES * 16];    // [n][o]    fp32: v@root + bias (node-local term)
__device__ float  g_sum[N_NODES * 16];  // scatter accumulator (zeroed in k_node_pre)
__device__ float  g_cnt[N_NODES];       // degree accumulator (zero-init; re-zeroed by k_finalbn cleanup)
__device__ float  g_s1[16];             // batch sum per feature
__device__ float  g_s2[16];             // batch sum-of-squares per feature
__device__ int    g_ctr;                // grid-barrier counter

// ---------------------------------------------------------------------------
// K1 (launch 1): per-node precompute of t/tb/r + g_sum zeroing + dst-degree
// histogram INTERLEAVED into the node loop (1 prefetched LDG + fire-and-forget
// RED per pair-iteration; fills latency stall slots, no tail phase).
// g_cnt arrives zeroed (initial module state / k_finalbn cleanup).
// ---------------------------------------------------------------------------
__global__ void __launch_bounds__(256, 3) k_node_pre(
    const float* __restrict__ v,
    const float* __restrict__ enet_w,   // [256][4]
    const float* __restrict__ enet_b,   // [256]
    const float* __restrict__ root,     // [16][16] (i,o)
    const float* __restrict__ bias,     // [16]
    const int*   __restrict__ ei)       // [2][E]
{
    int t = threadIdx.x;
    int lane = t & 31;
    int warp = t >> 5;
    int cp = lane >> 4;        // which c-pair (0: c0,c1 / 1: c2,c3)
    int o = lane & 15;

    // --- zero g_sum + BN stats ---
    unsigned gid = blockIdx.x * 256u + t;
    const float4 z4 = make_float4(0.f, 0.f, 0.f, 0.f);
    for (unsigned i = gid; i < N4; i += NP_TSTRIDE)
        reinterpret_cast<float4*>(g_sum)[i] = z4;
    if (gid < 16) { g_s1[gid] = 0.0f; g_s2[gid] = 0.0f; }
    if (gid == 16) g_ctr = 0;

    // --- register-resident weights ---
    float w0[16], w1[16], br[16];
    const float* brbase = (cp == 0) ? enet_b : root;
#pragma unroll
    for (int i = 0; i < 16; i++) {
        int j = i * 16 + o;
        float2 wp = __ldg(reinterpret_cast<const float2*>(enet_w + j * 4 + cp * 2));
        w0[i] = wp.x;
        w1[i] = wp.y;
        br[i] = __ldg(brbase + j);
    }
    float b0 = (cp == 0) ? 0.0f : bias[o];   // r accumulates bias; tb starts at 0

    // --- histogram cursor (grid-stride, coalesced per step; prefetch 1 ahead) ---
    const int* dstp = ei + N_EDGES;
    unsigned hi = gid;
    int nextdst = (hi < N_EDGES) ? __ldg(dstp + hi) : -1;

    // --- node loop: 2 nodes in flight per warp ---
    int wg = blockIdx.x * 8 + warp;
    for (int n0 = wg; n0 < N_NODES; n0 += 2 * NP_WARPS) {
        // interleaved histogram step (fire-and-forget RED, dst prefetched)
        if (nextdst >= 0) {
            float* cptr = g_cnt + nextdst;
            hi += NP_TSTRIDE;
            nextdst = (hi < N_EDGES) ? __ldg(dstp + hi) : -1;
            asm volatile("red.global.add.f32 [%0], %1;" :: "l"(cptr), "f"(1.0f) : "memory");
        }

        int n1 = n0 + NP_WARPS;
        bool has1 = (n1 < N_NODES);
        int n1c = has1 ? n1 : n0;

        const float4* vp0 = reinterpret_cast<const float4*>(v + (unsigned)n0 * 16u);
        const float4* vp1 = reinterpret_cast<const float4*>(v + (unsigned)n1c * 16u);
        float4 A0 = __ldg(vp0), A1 = __ldg(vp0 + 1), A2 = __ldg(vp0 + 2), A3 = __ldg(vp0 + 3);
        float4 B0 = __ldg(vp1), B1 = __ldg(vp1 + 1), B2 = __ldg(vp1 + 2), B3 = __ldg(vp1 + 3);

        float va[16] = {A0.x, A0.y, A0.z, A0.w, A1.x, A1.y, A1.z, A1.w,
                        A2.x, A2.y, A2.z, A2.w, A3.x, A3.y, A3.z, A3.w};
        float vb[16] = {B0.x, B0.y, B0.z, B0.w, B1.x, B1.y, B1.z, B1.w,
                        B2.x, B2.y, B2.z, B2.w, B3.x, B3.y, B3.z, B3.w};

        float x0 = 0.f, x1 = 0.f, xb = b0;
        float y0 = 0.f, y1 = 0.f, yb = b0;
#pragma unroll
        for (int i = 0; i < 16; i++) {
            x0 = fmaf(va[i], w0[i], x0);
            y0 = fmaf(vb[i], w0[i], y0);
            x1 = fmaf(va[i], w1[i], x1);
            y1 = fmaf(vb[i], w1[i], y1);
            xb = fmaf(va[i], br[i], xb);
            yb = fmaf(vb[i], br[i], yb);
        }

        {
            __half2 h = __floats2half2_rn(x0, x1);
            *reinterpret_cast<__half2*>(g_t + (unsigned)n0 * 64u + o * 4u + cp * 2u) = h;
            if (cp == 0) g_tb[(unsigned)n0 * 16u + o] = __float2half_rn(xb);
            else         g_r[(unsigned)n0 * 16u + o] = xb;
        }
        if (has1) {
            __half2 h = __floats2half2_rn(y0, y1);
            *reinterpret_cast<__half2*>(g_t + (unsigned)n1 * 64u + o * 4u + cp * 2u) = h;
            if (cp == 0) g_tb[(unsigned)n1 * 16u + o] = __float2half_rn(yb);
            else         g_r[(unsigned)n1 * 16u + o] = yb;
        }
    }

    // --- drain any remaining histogram steps (rare: 9 steps vs ~14 iters) ---
    while (nextdst >= 0) {
        float* cptr = g_cnt + nextdst;
        hi += NP_TSTRIDE;
        nextdst = (hi < N_EDGES) ? __ldg(dstp + hi) : -1;
        asm volatile("red.global.add.f32 [%0], %1;" :: "l"(cptr), "f"(1.0f) : "memory");
    }
}

// ---------------------------------------------------------------------------
// K2 (launch 2): per-edge message + vector RED scatter (R12 form, minus the
// per-edge degree RED). Quad of 4 threads per edge; thread j -> outputs 4j..4j+3.
// ---------------------------------------------------------------------------
__global__ void __launch_bounds__(256) k_edge(
    const float* __restrict__ efeat,
    const int* __restrict__ ei)   // [2][E] row0=src, row1=dst
{
    unsigned gid = blockIdx.x * 256u + threadIdx.x;
    unsigned eid = gid >> 2;
    unsigned j = gid & 3u;

    int src = __ldg(ei + eid);
    int dst = __ldg(ei + N_EDGES + eid);

    float4 ev = __ldg(reinterpret_cast<const float4*>(efeat) + eid);

    const uint4* tp = reinterpret_cast<const uint4*>(g_t + (unsigned)src * 64u + j * 16u);
    uint4 ta = __ldg(tp);
    uint4 tb = __ldg(tp + 1);
    uint2 tbr = __ldg(reinterpret_cast<const uint2*>(g_tb + (unsigned)src * 16u + j * 4u));

#define H2F(u) __half22float2(*reinterpret_cast<__half2*>(&(u)))
    float2 b01 = H2F(tbr.x), b23 = H2F(tbr.y);
    float2 c0 = H2F(ta.x), c1 = H2F(ta.y), c2 = H2F(ta.z), c3 = H2F(ta.w);
    float2 c4 = H2F(tb.x), c5 = H2F(tb.y), c6 = H2F(tb.z), c7 = H2F(tb.w);
#undef H2F
    float m0 = fmaf(ev.x, c0.x, fmaf(ev.y, c0.y, fmaf(ev.z, c1.x, fmaf(ev.w, c1.y, b01.x))));
    float m1 = fmaf(ev.x, c2.x, fmaf(ev.y, c2.y, fmaf(ev.z, c3.x, fmaf(ev.w, c3.y, b01.y))));
    float m2 = fmaf(ev.x, c4.x, fmaf(ev.y, c4.y, fmaf(ev.z, c5.x, fmaf(ev.w, c5.y, b23.x))));
    float m3 = fmaf(ev.x, c6.x, fmaf(ev.y, c6.y, fmaf(ev.z, c7.x, fmaf(ev.w, c7.y, b23.y))));

    float* outp = g_sum + (unsigned)dst * 16u + j * 4u;
    asm volatile("red.global.add.v4.f32 [%0], {%1, %2, %3, %4};"
                 :: "l"(outp), "f"(m0), "f"(m1), "f"(m2), "f"(m3) : "memory");
}

// ---------------------------------------------------------------------------
// K3 (launch 3): fused finalize + BatchNorm + LeakyReLU with software grid
// barrier (592 blocks <= full residency). Cleans g_cnt after reading so the
// next launch/replay starts from a zeroed histogram.
// ---------------------------------------------------------------------------
__global__ void __launch_bounds__(256) k_finalbn(
    float* __restrict__ out,
    const float* __restrict__ gamma,
    const float* __restrict__ beta)
{
    int t = threadIdx.x;
    int idx = blockIdx.x * 256 + t;
    const float4* s4 = reinterpret_cast<const float4*>(g_sum);
    const float4* r4 = reinterpret_cast<const float4*>(g_r);
    float4* o4 = reinterpret_cast<float4*>(out);

    float4 vals[3];
    float s1x = 0.f, s1y = 0.f, s1z = 0.f, s1w = 0.f;
    float s2x = 0.f, s2y = 0.f, s2z = 0.f, s2w = 0.f;
#pragma unroll
    for (int k = 0; k < 3; k++) {
        int i = idx + k * FB_STRIDE;
        if (i < N4) {
            int n = i >> 2;
            float cnt = g_cnt[n];
            float inv = 1.0f / fmaxf(cnt, 1.0f);
            float4 s = s4[i];
            float4 r = r4[i];
            if ((i & 3) == 0) g_cnt[n] = 0.0f;   // cleanup for next launch
            float4 val;
            val.x = fmaf(s.x, inv, r.x);
            val.y = fmaf(s.y, inv, r.y);
            val.z = fmaf(s.z, inv, r.z);
            val.w = fmaf(s.w, inv, r.w);
            vals[k] = val;
            s1x += val.x; s1y += val.y; s1z += val.z; s1w += val.w;
            s2x = fmaf(val.x, val.x, s2x);
            s2y = fmaf(val.y, val.y, s2y);
            s2z = fmaf(val.z, val.z, s2z);
            s2w = fmaf(val.w, val.w, s2w);
        }
    }

#pragma unroll
    for (int m = 4; m <= 16; m <<= 1) {
        s1x += __shfl_xor_sync(0xffffffffu, s1x, m);
        s1y += __shfl_xor_sync(0xffffffffu, s1y, m);
        s1z += __shfl_xor_sync(0xffffffffu, s1z, m);
        s1w += __shfl_xor_sync(0xffffffffu, s1w, m);
        s2x += __shfl_xor_sync(0xffffffffu, s2x, m);
        s2y += __shfl_xor_sync(0xffffffffu, s2y, m);
        s2z += __shfl_xor_sync(0xffffffffu, s2z, m);
        s2w += __shfl_xor_sync(0xffffffffu, s2w, m);
    }
    __shared__ float sm1[8][4][4];
    __shared__ float sm2[8][4][4];
    int warp = t >> 5;
    int lane = t & 31;
    if (lane < 4) {
        sm1[warp][lane][0] = s1x; sm1[warp][lane][1] = s1y;
        sm1[warp][lane][2] = s1z; sm1[warp][lane][3] = s1w;
        sm2[warp][lane][0] = s2x; sm2[warp][lane][1] = s2y;
        sm2[warp][lane][2] = s2z; sm2[warp][lane][3] = s2w;
    }
    __syncthreads();
    if (t < 16) {
        float a1 = 0.f, a2 = 0.f;
#pragma unroll
        for (int w = 0; w < 8; w++) {
            a1 += sm1[w][t >> 2][t & 3];
            a2 += sm2[w][t >> 2][t & 3];
        }
        atomicAdd(&g_s1[t], a1);
        atomicAdd(&g_s2[t], a2);
    }

    __threadfence();
    __syncthreads();
    if (t == 0) {
        atomicAdd(&g_ctr, 1);
        while (atomicAdd(&g_ctr, 0) < FB_GRID) { }
    }
    __syncthreads();

    int ob = (idx & 3) * 4;
    const float invN = 1.0f / (float)N_NODES;
    float scale[4], shift[4];
#pragma unroll
    for (int k = 0; k < 4; k++) {
        int o = ob + k;
        float mu = __ldcg(&g_s1[o]) * invN;
        float var = __ldcg(&g_s2[o]) * invN - mu * mu;
        float sc = gamma[o] * rsqrtf(var + 1e-5f);
        scale[k] = sc;
        shift[k] = beta[o] - sc * mu;
    }
#pragma unroll
    for (int k = 0; k < 3; k++) {
        int i = idx + k * FB_STRIDE;
        if (i < N4) {
            float4 val = vals[k];
            float x0 = fmaf(val.x, scale[0], shift[0]);
            float x1 = fmaf(val.y, scale[1], shift[1]);
            float x2 = fmaf(val.z, scale[2], shift[2]);
            float x3 = fmaf(val.w, scale[3], shift[3]);
            float4 res;
            res.x = (x0 >= 0.0f) ? x0 : 0.01f * x0;
            res.y = (x1 >= 0.0f) ? x1 : 0.01f * x1;
            res.z = (x2 >= 0.0f) ? x2 : 0.01f * x2;
            res.w = (x3 >= 0.0f) ? x3 : 0.01f * x3;
            o4[i] = res;
        }
    }
}

// ---------------------------------------------------------------------------
extern "C" void kernel_launch(void* const* d_in, const int* in_sizes, int n_in,
                              void* d_out, int out_size) {
    const float* v      = (const float*)d_in[0];
    const float* e      = (const float*)d_in[1];
    const int*   ei     = (const int*)  d_in[2];
    const float* enet_w = (const float*)d_in[3];
    const float* enet_b = (const float*)d_in[4];
    const float* root   = (const float*)d_in[5];
    const float* bias   = (const float*)d_in[6];
    const float* gamma  = (const float*)d_in[7];
    const float* beta   = (const float*)d_in[8];
    float* out = (float*)d_out;

    k_node_pre<<<NP_GRID, 256>>>(v, enet_w, enet_b, root, bias, ei);  // launch 1
    k_edge    <<<(N_EDGES * 4) / 256, 256>>>(e, ei);                  // launch 2
    k_finalbn <<<FB_GRID, 256>>>(out, gamma, beta);                   // launch 3
}

// round 16
// speedup vs baseline: 1.2079x; 1.0531x over previous
#include <cuda_runtime.h>
#include <cuda_fp16.h>

#define N_NODES 100000
#define N_EDGES 1000000
#define FB_GRID 592
#define FB_STRIDE (FB_GRID * 256)          // 151552
#define N4 (N_NODES * 4)                   // 400000 float4 slots
#define NP_GRID 444                        // 148 SMs x 3 CTAs
#define NP_WARPS (NP_GRID * 8)             // 3552 warps
#define NP_TSTRIDE (NP_GRID * 256u)        // 113664 threads

__device__ __half g_t[N_NODES * 64];    // [n][o][c] fp16: t[n,o,c] = sum_i v[n,i]*W[i*16+o][c]
__device__ __half g_tb[N_NODES * 16];   // [n][o]    fp16: tb[n,o] = sum_i v[n,i]*b[i*16+o]
__device__ float  g_r[N_NODES * 16];    // [n][o]    fp32: v@root + bias (node-local term)
__device__ float  g_sum[N_NODES * 16];  // scatter accumulator (zeroed in k_node_pre)
__device__ float  g_cnt[N_NODES];       // degree accumulator (zeroed in k_node_pre)
__device__ float  g_s1[16];             // batch sum per feature
__device__ float  g_s2[16];             // batch sum-of-squares per feature
__device__ int    g_ctr;                // grid-barrier counter

// ---------------------------------------------------------------------------
// K1 (launch 1): per-node precompute of t/tb/r + zeroing (R12 work placement).
// One warp per node-pair; lane = (cp, o). Weights register-resident.
// NEW: v rows software-pipelined through shared memory via cp.async
// (depth-1 double buffer per warp) so DRAM/L2 load latency is hidden
// behind the previous pair's FMA work.
// ---------------------------------------------------------------------------
__global__ void __launch_bounds__(256, 3) k_node_pre(
    const float* __restrict__ v,
    const float* __restrict__ enet_w,   // [256][4]
    const float* __restrict__ enet_b,   // [256]
    const float* __restrict__ root,     // [16][16] (i,o)
    const float* __restrict__ bias)     // [16]
{
    __shared__ __align__(16) float sbuf[2][8][32];   // [buf][warp][2 nodes x 16 floats]
    int t = threadIdx.x;
    int lane = t & 31;
    int warp = t >> 5;
    int cp = lane >> 4;        // which c-pair (0: c0,c1 / 1: c2,c3)
    int o = lane & 15;

    // --- zero g_sum, g_cnt, BN stats, barrier counter ---
    unsigned gid = blockIdx.x * 256u + t;
    const float4 z4 = make_float4(0.f, 0.f, 0.f, 0.f);
    for (unsigned i = gid; i < N4; i += NP_TSTRIDE)
        reinterpret_cast<float4*>(g_sum)[i] = z4;
    for (unsigned i = gid; i < N_NODES; i += NP_TSTRIDE) g_cnt[i] = 0.0f;
    if (gid < 16) { g_s1[gid] = 0.0f; g_s2[gid] = 0.0f; }
    if (gid == 16) g_ctr = 0;

    // --- register-resident weights ---
    float w0[16], w1[16], br[16];
    const float* brbase = (cp == 0) ? enet_b : root;
#pragma unroll
    for (int i = 0; i < 16; i++) {
        int j = i * 16 + o;
        float2 wp = __ldg(reinterpret_cast<const float2*>(enet_w + j * 4 + cp * 2));
        w0[i] = wp.x;
        w1[i] = wp.y;
        br[i] = __ldg(brbase + j);
    }
    float b0 = (cp == 0) ? 0.0f : bias[o];   // r accumulates bias; tb starts at 0

    int wg = blockIdx.x * 8 + warp;

    // prefetch helper: stage pair p's two v rows (128B) into sbuf[b][warp]
    // lanes 0-3: node n0 (16B each), lanes 4-7: node n1. Always commits.
    auto prefetch = [&](int p, int b) {
        int n0 = wg + p * (2 * NP_WARPS);
        if (n0 >= N_NODES) n0 = 0;                    // dummy (never consumed)
        int n1 = n0 + NP_WARPS;
        if (n1 >= N_NODES) n1 = n0;
        if (lane < 8) {
            const float* src = (lane < 4)
                ? (v + (unsigned)n0 * 16u + lane * 4)
                : (v + (unsigned)n1 * 16u + (lane - 4) * 4);
            unsigned dst = (unsigned)__cvta_generic_to_shared(&sbuf[b][warp][lane * 4]);
            asm volatile("cp.async.cg.shared.global [%0], [%1], 16;"
                         :: "r"(dst), "l"(src) : "memory");
        }
        asm volatile("cp.async.commit_group;" ::: "memory");
    };

    prefetch(0, 0);
    int buf = 0;
    int p = 0;
    for (int n0 = wg; n0 < N_NODES; n0 += 2 * NP_WARPS, p++) {
        prefetch(p + 1, buf ^ 1);                     // next pair in flight
        asm volatile("cp.async.wait_group 1;" ::: "memory");
        __syncwarp();

        int n1 = n0 + NP_WARPS;
        bool has1 = (n1 < N_NODES);

        const float4* bufA = reinterpret_cast<const float4*>(&sbuf[buf][warp][0]);
        const float4* bufB = reinterpret_cast<const float4*>(&sbuf[buf][warp][16]);

        float x0 = 0.f, x1 = 0.f, xb = b0;
        float y0 = 0.f, y1 = 0.f, yb = b0;
#pragma unroll
        for (int q = 0; q < 4; q++) {
            float4 xa = bufA[q];          // LDS.128, uniform broadcast
            float4 xv = bufB[q];
            int i = q * 4;
            x0 = fmaf(xa.x, w0[i+0], x0); y0 = fmaf(xv.x, w0[i+0], y0);
            x1 = fmaf(xa.x, w1[i+0], x1); y1 = fmaf(xv.x, w1[i+0], y1);
            xb = fmaf(xa.x, br[i+0], xb); yb = fmaf(xv.x, br[i+0], yb);
            x0 = fmaf(xa.y, w0[i+1], x0); y0 = fmaf(xv.y, w0[i+1], y0);
            x1 = fmaf(xa.y, w1[i+1], x1); y1 = fmaf(xv.y, w1[i+1], y1);
            xb = fmaf(xa.y, br[i+1], xb); yb = fmaf(xv.y, br[i+1], yb);
            x0 = fmaf(xa.z, w0[i+2], x0); y0 = fmaf(xv.z, w0[i+2], y0);
            x1 = fmaf(xa.z, w1[i+2], x1); y1 = fmaf(xv.z, w1[i+2], y1);
            xb = fmaf(xa.z, br[i+2], xb); yb = fmaf(xv.z, br[i+2], yb);
            x0 = fmaf(xa.w, w0[i+3], x0); y0 = fmaf(xv.w, w0[i+3], y0);
            x1 = fmaf(xa.w, w1[i+3], x1); y1 = fmaf(xv.w, w1[i+3], y1);
            xb = fmaf(xa.w, br[i+3], xb); yb = fmaf(xv.w, br[i+3], yb);
        }

        {
            __half2 h = __floats2half2_rn(x0, x1);
            *reinterpret_cast<__half2*>(g_t + (unsigned)n0 * 64u + o * 4u + cp * 2u) = h;
            if (cp == 0) g_tb[(unsigned)n0 * 16u + o] = __float2half_rn(xb);
            else         g_r[(unsigned)n0 * 16u + o] = xb;
        }
        if (has1) {
            __half2 h = __floats2half2_rn(y0, y1);
            *reinterpret_cast<__half2*>(g_t + (unsigned)n1 * 64u + o * 4u + cp * 2u) = h;
            if (cp == 0) g_tb[(unsigned)n1 * 16u + o] = __float2half_rn(yb);
            else         g_r[(unsigned)n1 * 16u + o] = yb;
        }
        buf ^= 1;
    }
}

// ---------------------------------------------------------------------------
// K2 (launch 2): per-edge message + vector RED scatter + degree RED.
// Quad of 4 threads per edge; thread j covers outputs 4j..4j+3. (R12-exact)
// ---------------------------------------------------------------------------
__global__ void __launch_bounds__(256) k_edge(
    const float* __restrict__ efeat,
    const int* __restrict__ ei)   // [2][E] row0=src, row1=dst
{
    unsigned gid = blockIdx.x * 256u + threadIdx.x;
    unsigned eid = gid >> 2;
    unsigned j = gid & 3u;

    int src = __ldg(ei + eid);
    int dst = __ldg(ei + N_EDGES + eid);

    float4 ev = __ldg(reinterpret_cast<const float4*>(efeat) + eid);

    const uint4* tp = reinterpret_cast<const uint4*>(g_t + (unsigned)src * 64u + j * 16u);
    uint4 ta = __ldg(tp);
    uint4 tb = __ldg(tp + 1);
    uint2 tbr = __ldg(reinterpret_cast<const uint2*>(g_tb + (unsigned)src * 16u + j * 4u));

#define H2F(u) __half22float2(*reinterpret_cast<__half2*>(&(u)))
    float2 b01 = H2F(tbr.x), b23 = H2F(tbr.y);
    float2 c0 = H2F(ta.x), c1 = H2F(ta.y), c2 = H2F(ta.z), c3 = H2F(ta.w);
    float2 c4 = H2F(tb.x), c5 = H2F(tb.y), c6 = H2F(tb.z), c7 = H2F(tb.w);
#undef H2F
    float m0 = fmaf(ev.x, c0.x, fmaf(ev.y, c0.y, fmaf(ev.z, c1.x, fmaf(ev.w, c1.y, b01.x))));
    float m1 = fmaf(ev.x, c2.x, fmaf(ev.y, c2.y, fmaf(ev.z, c3.x, fmaf(ev.w, c3.y, b01.y))));
    float m2 = fmaf(ev.x, c4.x, fmaf(ev.y, c4.y, fmaf(ev.z, c5.x, fmaf(ev.w, c5.y, b23.x))));
    float m3 = fmaf(ev.x, c6.x, fmaf(ev.y, c6.y, fmaf(ev.z, c7.x, fmaf(ev.w, c7.y, b23.y))));

    float* outp = g_sum + (unsigned)dst * 16u + j * 4u;
    asm volatile("red.global.add.v4.f32 [%0], {%1, %2, %3, %4};"
                 :: "l"(outp), "f"(m0), "f"(m1), "f"(m2), "f"(m3) : "memory");
    if (j == 0) {
        float* cptr = g_cnt + dst;
        asm volatile("red.global.add.f32 [%0], %1;" :: "l"(cptr), "f"(1.0f) : "memory");
    }
}

// ---------------------------------------------------------------------------
// K3 (launch 3): fused finalize + BatchNorm + LeakyReLU with software grid
// barrier (592 blocks <= full residency; cannot deadlock). (R12-exact)
// ---------------------------------------------------------------------------
__global__ void __launch_bounds__(256) k_finalbn(
    float* __restrict__ out,
    const float* __restrict__ gamma,
    const float* __restrict__ beta)
{
    int t = threadIdx.x;
    int idx = blockIdx.x * 256 + t;
    const float4* s4 = reinterpret_cast<const float4*>(g_sum);
    const float4* r4 = reinterpret_cast<const float4*>(g_r);
    float4* o4 = reinterpret_cast<float4*>(out);

    float4 vals[3];
    float s1x = 0.f, s1y = 0.f, s1z = 0.f, s1w = 0.f;
    float s2x = 0.f, s2y = 0.f, s2z = 0.f, s2w = 0.f;
#pragma unroll
    for (int k = 0; k < 3; k++) {
        int i = idx + k * FB_STRIDE;
        if (i < N4) {
            int n = i >> 2;
            float inv = 1.0f / fmaxf(g_cnt[n], 1.0f);
            float4 s = s4[i];
            float4 r = r4[i];
            float4 val;
            val.x = fmaf(s.x, inv, r.x);
            val.y = fmaf(s.y, inv, r.y);
            val.z = fmaf(s.z, inv, r.z);
            val.w = fmaf(s.w, inv, r.w);
            vals[k] = val;
            s1x += val.x; s1y += val.y; s1z += val.z; s1w += val.w;
            s2x = fmaf(val.x, val.x, s2x);
            s2y = fmaf(val.y, val.y, s2y);
            s2z = fmaf(val.z, val.z, s2z);
            s2w = fmaf(val.w, val.w, s2w);
        }
    }

#pragma unroll
    for (int m = 4; m <= 16; m <<= 1) {
        s1x += __shfl_xor_sync(0xffffffffu, s1x, m);
        s1y += __shfl_xor_sync(0xffffffffu, s1y, m);
        s1z += __shfl_xor_sync(0xffffffffu, s1z, m);
        s1w += __shfl_xor_sync(0xffffffffu, s1w, m);
        s2x += __shfl_xor_sync(0xffffffffu, s2x, m);
        s2y += __shfl_xor_sync(0xffffffffu, s2y, m);
        s2z += __shfl_xor_sync(0xffffffffu, s2z, m);
        s2w += __shfl_xor_sync(0xffffffffu, s2w, m);
    }
    __shared__ float sm1[8][4][4];
    __shared__ float sm2[8][4][4];
    int warp = t >> 5;
    int lane = t & 31;
    if (lane < 4) {
        sm1[warp][lane][0] = s1x; sm1[warp][lane][1] = s1y;
        sm1[warp][lane][2] = s1z; sm1[warp][lane][3] = s1w;
        sm2[warp][lane][0] = s2x; sm2[warp][lane][1] = s2y;
        sm2[warp][lane][2] = s2z; sm2[warp][lane][3] = s2w;
    }
    __syncthreads();
    if (t < 16) {
        float a1 = 0.f, a2 = 0.f;
#pragma unroll
        for (int w = 0; w < 8; w++) {
            a1 += sm1[w][t >> 2][t & 3];
            a2 += sm2[w][t >> 2][t & 3];
        }
        atomicAdd(&g_s1[t], a1);
        atomicAdd(&g_s2[t], a2);
    }

    __threadfence();
    __syncthreads();
    if (t == 0) {
        atomicAdd(&g_ctr, 1);
        while (atomicAdd(&g_ctr, 0) < FB_GRID) { }
    }
    __syncthreads();

    int ob = (idx & 3) * 4;
    const float invN = 1.0f / (float)N_NODES;
    float scale[4], shift[4];
#pragma unroll
    for (int k = 0; k < 4; k++) {
        int o = ob + k;
        float mu = __ldcg(&g_s1[o]) * invN;
        float var = __ldcg(&g_s2[o]) * invN - mu * mu;
        float sc = gamma[o] * rsqrtf(var + 1e-5f);
        scale[k] = sc;
        shift[k] = beta[o] - sc * mu;
    }
#pragma unroll
    for (int k = 0; k < 3; k++) {
        int i = idx + k * FB_STRIDE;
        if (i < N4) {
            float4 val = vals[k];
            float x0 = fmaf(val.x, scale[0], shift[0]);
            float x1 = fmaf(val.y, scale[1], shift[1]);
            float x2 = fmaf(val.z, scale[2], shift[2]);
            float x3 = fmaf(val.w, scale[3], shift[3]);
            float4 res;
            res.x = (x0 >= 0.0f) ? x0 : 0.01f * x0;
            res.y = (x1 >= 0.0f) ? x1 : 0.01f * x1;
            res.z = (x2 >= 0.0f) ? x2 : 0.01f * x2;
            res.w = (x3 >= 0.0f) ? x3 : 0.01f * x3;
            o4[i] = res;
        }
    }
}

// ---------------------------------------------------------------------------
extern "C" void kernel_launch(void* const* d_in, const int* in_sizes, int n_in,
                              void* d_out, int out_size) {
    const float* v      = (const float*)d_in[0];
    const float* e      = (const float*)d_in[1];
    const int*   ei     = (const int*)  d_in[2];
    const float* enet_w = (const float*)d_in[3];
    const float* enet_b = (const float*)d_in[4];
    const float* root   = (const float*)d_in[5];
    const float* bias   = (const float*)d_in[6];
    const float* gamma  = (const float*)d_in[7];
    const float* beta   = (const float*)d_in[8];
    float* out = (float*)d_out;

    k_node_pre<<<NP_GRID, 256>>>(v, enet_w, enet_b, root, bias);  // launch 1
    k_edge    <<<(N_EDGES * 4) / 256, 256>>>(e, ei);              // launch 2
    k_finalbn <<<FB_GRID, 256>>>(out, gamma, beta);               // launch 3
}